// round 2
// baseline (speedup 1.0000x reference)
#include <cuda_runtime.h>
#include <math.h>

// ---------------------------------------------------------------------------
//   x:  (32, 3, 512, 512)
//   h1: (32, 4, 256, 256)   conv1(3x3,SAME)+ReLU+avgpool2
//   (h2 eliminated: NetVLAD fused into conv2 kernel)
//   NetVLAD: K=4, D=16, M=16384 pixels/image
//   out: (32, 7)
// ---------------------------------------------------------------------------

#define NIMG   32
#define NPART  128         // partials per image = conv2 blocks per image (one per row)
#define M2     16384
#define EPSN   1e-12f

__device__ float g_h1[NIMG * 4 * 256 * 256];       // 33.5 MB scratch
__device__ float g_part[NIMG * NPART * 68];        // vlad partials

// ---- packed f32x2 helpers (Blackwell FFMA2 path; u64 register-pair carrier) --
typedef unsigned long long u64;

__device__ __forceinline__ u64 pack2(float lo, float hi) {
    u64 d; asm("mov.b64 %0, {%1,%2};" : "=l"(d) : "f"(lo), "f"(hi)); return d;
}
__device__ __forceinline__ void unpack2(u64 d, float& lo, float& hi) {
    asm("mov.b64 {%0,%1}, %2;" : "=f"(lo), "=f"(hi) : "l"(d));
}
__device__ __forceinline__ u64 ffma2(u64 a, u64 b, u64 c) {
    u64 d; asm("fma.rn.f32x2 %0, %1, %2, %3;" : "=l"(d) : "l"(a), "l"(b), "l"(c));
    return d;
}

// ---------------------------------------------------------------------------
// Kernel 1: conv1 (3->4) + ReLU + pool. One thread = one pooled pixel.
// px-pair packed into f32x2; weights pre-packed {w,w} in shared.
// grid (1, 256, 32), block 256
// ---------------------------------------------------------------------------
__global__ __launch_bounds__(256) void conv1_pool_kernel(
    const float* __restrict__ x,
    const float* __restrict__ w,
    const float* __restrict__ bias)
{
    __shared__ u64 sw2[108];    // (4,3,3,3) packed {w,w}
    __shared__ u64 sb2[4];
    int t = threadIdx.x;
    if (t < 108) { float v = w[t]; sw2[t] = pack2(v, v); }
    if (t < 4)   { float v = bias[t]; sb2[t] = pack2(v, v); }
    __syncthreads();

    int ox = t;                 // 0..255
    int oy = blockIdx.y;        // 0..255
    int n  = blockIdx.z;

    const float* xb = x + n * 3 * 512 * 512;
    int iy0 = 2 * oy - 1;
    int ix0 = 2 * ox - 1;

    // packed shifted patch rows: pk[ic][dy][s] = (p[s], p[s+1]) for px 0/1
    u64 pk[3][4][3];
#pragma unroll
    for (int ic = 0; ic < 3; ic++) {
#pragma unroll
        for (int dy = 0; dy < 4; dy++) {
            int iy = iy0 + dy;
            bool okY = (iy >= 0) && (iy < 512);
            const float* row = xb + ic * 262144 + iy * 512;
            float p0 = (okY && ix0 >= 0)      ? __ldg(row + ix0)     : 0.0f;
            float p1 = okY                    ? __ldg(row + ix0 + 1) : 0.0f;
            float p2 = okY                    ? __ldg(row + ix0 + 2) : 0.0f;
            float p3 = (okY && ix0 + 3 < 512) ? __ldg(row + ix0 + 3) : 0.0f;
            pk[ic][dy][0] = pack2(p0, p1);
            pk[ic][dy][1] = pack2(p1, p2);
            pk[ic][dy][2] = pack2(p2, p3);
        }
    }

    float* ob = g_h1 + n * 4 * 65536 + oy * 256 + ox;
#pragma unroll
    for (int oc = 0; oc < 4; oc++) {
        u64 a0 = sb2[oc];   // conv positions (py=0, px=0/1)
        u64 a1 = sb2[oc];   // (py=1, px=0/1)
#pragma unroll
        for (int ic = 0; ic < 3; ic++)
#pragma unroll
            for (int ky = 0; ky < 3; ky++)
#pragma unroll
                for (int kx = 0; kx < 3; kx++) {
                    u64 w2 = sw2[((oc * 3 + ic) * 3 + ky) * 3 + kx];
                    a0 = ffma2(pk[ic][ky][kx],     w2, a0);
                    a1 = ffma2(pk[ic][ky + 1][kx], w2, a1);
                }
        float v00, v01, v10, v11;
        unpack2(a0, v00, v01);
        unpack2(a1, v10, v11);
        float s = fmaxf(v00, 0.0f) + fmaxf(v01, 0.0f)
                + fmaxf(v10, 0.0f) + fmaxf(v11, 0.0f);
        ob[oc * 65536] = s * 0.25f;
    }
}

// ---------------------------------------------------------------------------
// Kernel 2: conv2 (4->16) + ReLU + pool + NetVLAD assignment, fully fused.
// One thread = one pooled pixel (all 16 channels) -> softmax -> vlad contrib.
// Block (oy, n) reduces its 128 pixels to a 68-float partial (fixed order).
// grid (128, 32), block 128
// ---------------------------------------------------------------------------
__global__ __launch_bounds__(128) void conv2_vlad_kernel(
    const float* __restrict__ w,     // (16,4,3,3)
    const float* __restrict__ bias,  // (16,)
    const float* __restrict__ aw,    // (4,16)
    const float* __restrict__ ab)    // (4,)
{
    __shared__ u64   sw2[576];
    __shared__ u64   sb2[16];
    __shared__ float saw[64];
    __shared__ float sab[4];
    __shared__ float sred[4][68];

    int t = threadIdx.x;
    for (int i = t; i < 576; i += 128) { float v = w[i]; sw2[i] = pack2(v, v); }
    if (t < 16) { float v = bias[t]; sb2[t] = pack2(v, v); }
    if (t < 64) saw[t] = aw[t];
    if (t < 4)  sab[t] = ab[t];
    __syncthreads();

    int ox = t;                  // 0..127
    int oy = blockIdx.x;         // 0..127
    int n  = blockIdx.y;

    const float* xb = g_h1 + n * 4 * 65536;
    int iy0 = 2 * oy - 1;
    int ix0 = 2 * ox - 1;

    // packed accumulators: acc[oc][py] over px pair
    u64 acc[16][2];
#pragma unroll
    for (int oc = 0; oc < 16; oc++) { acc[oc][0] = sb2[oc]; acc[oc][1] = sb2[oc]; }

#pragma unroll
    for (int ic = 0; ic < 4; ic++) {
        u64 pk[4][3];
#pragma unroll
        for (int dy = 0; dy < 4; dy++) {
            int iy = iy0 + dy;
            bool okY = (iy >= 0) && (iy < 256);
            const float* row = xb + ic * 65536 + iy * 256;
            float p0 = (okY && ix0 >= 0)      ? __ldg(row + ix0)     : 0.0f;
            float p1 = okY                    ? __ldg(row + ix0 + 1) : 0.0f;
            float p2 = okY                    ? __ldg(row + ix0 + 2) : 0.0f;
            float p3 = (okY && ix0 + 3 < 256) ? __ldg(row + ix0 + 3) : 0.0f;
            pk[dy][0] = pack2(p0, p1);
            pk[dy][1] = pack2(p1, p2);
            pk[dy][2] = pack2(p2, p3);
        }
#pragma unroll
        for (int oc = 0; oc < 16; oc++) {
#pragma unroll
            for (int ky = 0; ky < 3; ky++)
#pragma unroll
                for (int kx = 0; kx < 3; kx++) {
                    u64 w2 = sw2[(oc * 4 + ic) * 9 + ky * 3 + kx];
                    acc[oc][0] = ffma2(pk[ky][kx],     w2, acc[oc][0]);
                    acc[oc][1] = ffma2(pk[ky + 1][kx], w2, acc[oc][1]);
                }
        }
    }

    // ReLU + pool -> pooled feature vector xv[16]
    float xv[16];
#pragma unroll
    for (int oc = 0; oc < 16; oc++) {
        float v00, v01, v10, v11;
        unpack2(acc[oc][0], v00, v01);
        unpack2(acc[oc][1], v10, v11);
        xv[oc] = (fmaxf(v00, 0.0f) + fmaxf(v01, 0.0f)
                + fmaxf(v10, 0.0f) + fmaxf(v11, 0.0f)) * 0.25f;
    }

    // NetVLAD soft-assignment for this pixel
    float lg[4];
#pragma unroll
    for (int k = 0; k < 4; k++) {
        float v = sab[k];
#pragma unroll
        for (int c = 0; c < 16; c++) v = fmaf(saw[k * 16 + c], xv[c], v);
        lg[k] = v;
    }
    float mx = fmaxf(fmaxf(lg[0], lg[1]), fmaxf(lg[2], lg[3]));
    float e0 = __expf(lg[0] - mx), e1 = __expf(lg[1] - mx);
    float e2 = __expf(lg[2] - mx), e3 = __expf(lg[3] - mx);
    float inv = 1.0f / (e0 + e1 + e2 + e3);
    float a[4] = { e0 * inv, e1 * inv, e2 * inv, e3 * inv };

    // fixed-order block reduction of the 68 contributions
    int lane = t & 31, wid = t >> 5;
#pragma unroll
    for (int i = 0; i < 68; i++) {
        float v = (i < 64) ? a[i >> 4] * xv[i & 15] : a[i - 64];
#pragma unroll
        for (int o = 16; o > 0; o >>= 1) v += __shfl_down_sync(0xffffffffu, v, o);
        if (lane == 0) sred[wid][i] = v;
    }
    __syncthreads();

    if (t < 68) {
        float v = sred[0][t] + sred[1][t] + sred[2][t] + sred[3][t];
        g_part[(n * NPART + oy) * 68 + t] = v;
    }
}

// ---------------------------------------------------------------------------
// Kernel 3: finalize. grid = NIMG, block = 128.
// ---------------------------------------------------------------------------
__global__ void finalize_kernel(const float* __restrict__ cent,   // (4,16)
                                const float* __restrict__ lw,     // (7,64)
                                const float* __restrict__ lb,     // (7,)
                                float* __restrict__ out)          // (32,7)
{
    __shared__ float v[68];
    __shared__ float vn[64];
    __shared__ float norms[4];
    __shared__ float gnorm;

    int n = blockIdx.x;
    int t = threadIdx.x;

    if (t < 68) {
        const float* p = g_part + n * NPART * 68 + t;
        float s = 0.0f;
#pragma unroll 8
        for (int b = 0; b < NPART; b++) s += p[b * 68];
        v[t] = s;
    }
    __syncthreads();

    if (t < 64) {
        int k = t >> 4;
        vn[t] = v[t] - v[64 + k] * cent[t];
    }
    __syncthreads();

    if (t < 4) {
        float s = 0.0f;
#pragma unroll
        for (int c = 0; c < 16; c++) { float q = vn[t * 16 + c]; s += q * q; }
        norms[t] = fmaxf(sqrtf(s), EPSN);
    }
    __syncthreads();

    if (t < 64) vn[t] = vn[t] / norms[t >> 4];
    __syncthreads();

    if (t == 0) {
        float s = 0.0f;
#pragma unroll
        for (int i = 0; i < 64; i++) s += vn[i] * vn[i];
        gnorm = fmaxf(sqrtf(s), EPSN);
    }
    __syncthreads();

    if (t < 7) {
        float g = 1.0f / gnorm;
        float s = lb[t];
#pragma unroll
        for (int i = 0; i < 64; i++) s = fmaf(vn[i] * g, lw[t * 64 + i], s);
        out[n * 7 + t] = s;
    }
}

// ---------------------------------------------------------------------------
extern "C" void kernel_launch(void* const* d_in, const int* in_sizes, int n_in,
                              void* d_out, int out_size)
{
    const float* x    = (const float*)d_in[0];
    const float* c1w  = (const float*)d_in[1];
    const float* c1b  = (const float*)d_in[2];
    const float* c2w  = (const float*)d_in[3];
    const float* c2b  = (const float*)d_in[4];
    const float* cent = (const float*)d_in[5];
    const float* aw   = (const float*)d_in[6];
    const float* ab   = (const float*)d_in[7];
    const float* lw   = (const float*)d_in[8];
    const float* lb   = (const float*)d_in[9];
    float* out = (float*)d_out;

    dim3 g1(1, 256, NIMG);
    conv1_pool_kernel<<<g1, 256>>>(x, c1w, c1b);

    dim3 g2(128, NIMG);
    conv2_vlad_kernel<<<g2, 128>>>(c2w, c2b, aw, ab);

    finalize_kernel<<<NIMG, 128>>>(cent, lw, lb, out);
}